// round 5
// baseline (speedup 1.0000x reference)
#include <cuda_runtime.h>
#include <math.h>

// ---------------- problem constants ----------------
#define S_LEN 4096
#define BATCH 2
#define NHEAD 16
#define NKVH  4
#define HD    128
#define HDIM  2048      // NHEAD*HD
#define KVDIM 512       // NKVH*HD
#define GRP   1024      // g = S * 0.25
#define NG    4         // S / g
#define MROWS (BATCH*S_LEN)   // 8192

// ---------------- scratch (device globals: no cudaMalloc allowed) ----------------
__device__ float g_Q[(size_t)MROWS * HDIM];    // 64 MB
__device__ float g_K[(size_t)MROWS * KVDIM];   // 16 MB
__device__ float g_V[(size_t)MROWS * KVDIM];   // 16 MB
__device__ float g_O[(size_t)MROWS * HDIM];    // 64 MB
__device__ float g_cos[S_LEN * 64];
__device__ float g_sin[S_LEN * 64];

// ---------------- RoPE table ----------------
// Reference: inv_freq fp32, angle = t * inv_freq in fp32, then cos/sin.
// Compute inv_freq correctly-rounded (via double), form the fp32 angle the
// same way, then take the true cos/sin of that fp32 angle (double trig).
__global__ void rope_table_kernel() {
    int idx = blockIdx.x * 256 + threadIdx.x;
    if (idx >= S_LEN * 64) return;
    int pos = idx >> 6;
    int i   = idx & 63;
    double inv = pow(10000.0, -((double)(2 * i) / 128.0));
    float ang = (float)pos * (float)inv;
    g_cos[idx] = (float)cos((double)ang);
    g_sin[idx] = (float)sin((double)ang);
}

// ---------------- RoPE apply (in place on g_Q, g_K) ----------------
__global__ void rope_kernel(const int* __restrict__ pos_ids) {
    int row = blockIdx.x;            // b*S + s
    int pos = pos_ids[row];
    int tid = threadIdx.x;
    // Q: 16 heads * 64 pairs = 1024 pairs
    for (int p = tid; p < NHEAD * 64; p += 256) {
        int hh = p >> 6, i = p & 63;
        float c  = g_cos[pos * 64 + i];
        float sn = g_sin[pos * 64 + i];
        size_t ba = (size_t)row * HDIM + hh * HD + i;
        float x0 = g_Q[ba], x1 = g_Q[ba + 64];
        g_Q[ba]      = x0 * c - x1 * sn;
        g_Q[ba + 64] = x1 * c + x0 * sn;
    }
    // K: 4 heads * 64 pairs = 256 pairs
    for (int p = tid; p < NKVH * 64; p += 256) {
        int hh = p >> 6, i = p & 63;
        float c  = g_cos[pos * 64 + i];
        float sn = g_sin[pos * 64 + i];
        size_t ba = (size_t)row * KVDIM + hh * HD + i;
        float x0 = g_K[ba], x1 = g_K[ba + 64];
        g_K[ba]      = x0 * c - x1 * sn;
        g_K[ba + 64] = x1 * c + x0 * sn;
    }
}

// ---------------- classic fp32 SGEMM: C[M,N] = A[M,K] @ B[K,N] ----------------
// BM=BN=128, BK=8, 256 threads, 8x8 register tile per thread.
__global__ __launch_bounds__(256) void sgemm(const float* __restrict__ A,
                                             const float* __restrict__ B,
                                             float* __restrict__ C,
                                             int M, int N, int K) {
    __shared__ float As[8][128];
    __shared__ float Bs[8][128];
    int tid = threadIdx.x;
    int bm = blockIdx.y * 128, bn = blockIdx.x * 128;
    int arow = tid >> 1, acol = (tid & 1) * 4;
    int brow = tid >> 5, bcol = (tid & 31) * 4;
    int tx = tid & 15, ty = tid >> 4;

    const float* Ap = A + (size_t)(bm + arow) * K + acol;
    const float* Bp = B + (size_t)brow * N + bn + bcol;

    float acc[8][8];
#pragma unroll
    for (int i = 0; i < 8; i++)
#pragma unroll
        for (int j = 0; j < 8; j++) acc[i][j] = 0.f;

    for (int k0 = 0; k0 < K; k0 += 8) {
        float4 av = *(const float4*)(Ap + k0);
        float4 bv = *(const float4*)(Bp + (size_t)k0 * N);
        As[acol + 0][arow] = av.x;
        As[acol + 1][arow] = av.y;
        As[acol + 2][arow] = av.z;
        As[acol + 3][arow] = av.w;
        *(float4*)&Bs[brow][bcol] = bv;
        __syncthreads();
#pragma unroll
        for (int kk = 0; kk < 8; kk++) {
            float ra[8], rb[8];
            *(float4*)&ra[0] = *(const float4*)&As[kk][ty * 8];
            *(float4*)&ra[4] = *(const float4*)&As[kk][ty * 8 + 4];
            *(float4*)&rb[0] = *(const float4*)&Bs[kk][tx * 8];
            *(float4*)&rb[4] = *(const float4*)&Bs[kk][tx * 8 + 4];
#pragma unroll
            for (int i = 0; i < 8; i++)
#pragma unroll
                for (int j = 0; j < 8; j++) acc[i][j] += ra[i] * rb[j];
        }
        __syncthreads();
    }
#pragma unroll
    for (int i = 0; i < 8; i++) {
        float* cp = C + (size_t)(bm + ty * 8 + i) * N + bn + tx * 8;
        float4 v0 = make_float4(acc[i][0], acc[i][1], acc[i][2], acc[i][3]);
        float4 v1 = make_float4(acc[i][4], acc[i][5], acc[i][6], acc[i][7]);
        *(float4*)cp = v0;
        *(float4*)(cp + 4) = v1;
    }
}

// ---------------- flash attention over S2 groups ----------------
// grid (16 qtiles, 16 heads, 8 group-blocks), 256 threads.
// BM=BN=64. Smem: Qs[64][128], KV union (K^T[128][64] / V[64][128]), Ss[64][64]
#define FA_SMEM ((64 * 128 + 64 * 128 + 64 * 64) * 4)

__global__ __launch_bounds__(256, 1) void flash_kernel() {
    extern __shared__ float smf[];
    float* Qs = smf;                 // [64][128]
    float* KV = smf + 64 * 128;      // K^T: [d][c] stride 64  OR  V: [k][c] stride 128
    float* Ss = smf + 2 * 64 * 128;  // [64][64]

    int tid = threadIdx.x;
    int qt = blockIdx.x;      // query tile within group
    int h  = blockIdx.y;      // head
    int bg = blockIdx.z;      // b*NG + gi
    int b = bg >> 2, gi = bg & 3;
    int base = gi * GRP + ((h >= NHEAD / 2) ? (GRP / 2) : 0);  // S2 shift
    int kvh = h >> 2;                                          // GQA map

    const float* Qg = g_Q + (size_t)b * S_LEN * HDIM + h * HD;
    const float* Kg = g_K + (size_t)b * S_LEN * KVDIM + kvh * HD;
    const float* Vg = g_V + (size_t)b * S_LEN * KVDIM + kvh * HD;
    float* Og = g_O + (size_t)b * S_LEN * HDIM + h * HD;

    int tx = tid & 15, ty = tid >> 4;
    int ty4 = ty * 4;

    // load Q tile (coalesced float4)
#pragma unroll
    for (int it = 0; it < 8; it++) {
        int idx = it * 1024 + tid * 4;
        int r = idx >> 7, c = idx & 127;
        int srow = (base + qt * 64 + r) & (S_LEN - 1);
        *(float4*)&Qs[r * 128 + c] = *(const float4*)(Qg + (size_t)srow * HDIM + c);
    }

    float m[4], l[4], Oa[4][8];
#pragma unroll
    for (int i = 0; i < 4; i++) {
        m[i] = -1e30f;
        l[i] = 0.f;
#pragma unroll
        for (int j = 0; j < 8; j++) Oa[i][j] = 0.f;
    }

    for (int kt = 0; kt <= qt; kt++) {
        __syncthreads();  // prior PV / Q-load complete
        // ---- load K tile transposed: KV[d*64 + c] = K[c][d] ----
        {
            int r = tid & 63, dblk = tid >> 6;
            int srow = (base + kt * 64 + r) & (S_LEN - 1);
            const float* kp = Kg + (size_t)srow * KVDIM;
#pragma unroll
            for (int it = 0; it < 8; it++) {
                int d0 = dblk * 32 + it * 4;
                float4 v = *(const float4*)(kp + d0);
                KV[(d0 + 0) * 64 + r] = v.x;
                KV[(d0 + 1) * 64 + r] = v.y;
                KV[(d0 + 2) * 64 + r] = v.z;
                KV[(d0 + 3) * 64 + r] = v.w;
            }
        }
        __syncthreads();

        // ---- S = Q K^T (4x4 register tile per thread) ----
        float sa[4][4];
#pragma unroll
        for (int i = 0; i < 4; i++)
#pragma unroll
            for (int j = 0; j < 4; j++) sa[i][j] = 0.f;

        for (int d4 = 0; d4 < 128; d4 += 4) {
            float qa[4][4];
#pragma unroll
            for (int i = 0; i < 4; i++)
                *(float4*)qa[i] = *(const float4*)&Qs[(ty4 + i) * 128 + d4];
#pragma unroll
            for (int dd = 0; dd < 4; dd++) {
                float4 kvv = *(const float4*)&KV[(d4 + dd) * 64 + tx * 4];
#pragma unroll
                for (int i = 0; i < 4; i++) {
                    sa[i][0] += qa[i][dd] * kvv.x;
                    sa[i][1] += qa[i][dd] * kvv.y;
                    sa[i][2] += qa[i][dd] * kvv.z;
                    sa[i][3] += qa[i][dd] * kvv.w;
                }
            }
        }

        // ---- scale + causal mask + online softmax ----
        const float scale = 0.08838834764831845f;  // 1/sqrt(128)
        int qb = qt * 64 + ty4, kb = kt * 64 + tx * 4;
#pragma unroll
        for (int i = 0; i < 4; i++) {
#pragma unroll
            for (int j = 0; j < 4; j++) {
                float v = sa[i][j] * scale;
                if (kb + j > qb + i) v = -1e30f;
                sa[i][j] = v;
            }
            float mx = fmaxf(fmaxf(sa[i][0], sa[i][1]), fmaxf(sa[i][2], sa[i][3]));
#pragma unroll
            for (int o = 1; o < 16; o <<= 1)
                mx = fmaxf(mx, __shfl_xor_sync(0xffffffffu, mx, o));
            float mn = fmaxf(m[i], mx);
            float sc = expf(m[i] - mn);
            float rs = 0.f;
#pragma unroll
            for (int j = 0; j < 4; j++) {
                float p = expf(sa[i][j] - mn);
                sa[i][j] = p;
                rs += p;
            }
#pragma unroll
            for (int o = 1; o < 16; o <<= 1)
                rs += __shfl_xor_sync(0xffffffffu, rs, o);
            l[i] = l[i] * sc + rs;
            m[i] = mn;
#pragma unroll
            for (int j = 0; j < 8; j++) Oa[i][j] *= sc;
            *(float4*)&Ss[(ty4 + i) * 64 + tx * 4] = *(float4*)sa[i];
        }
        __syncthreads();  // Ss visible; done reading K from KV

        // ---- load V tile (normal layout, coalesced) ----
#pragma unroll
        for (int it = 0; it < 8; it++) {
            int idx = it * 1024 + tid * 4;
            int r = idx >> 7, c = idx & 127;
            int srow = (base + kt * 64 + r) & (S_LEN - 1);
            *(float4*)&KV[r * 128 + c] = *(const float4*)(Vg + (size_t)srow * KVDIM + c);
        }
        __syncthreads();

        // ---- O += P @ V (rows ty4..+3, cols tx*8..+7) ----
#pragma unroll 8
        for (int k = 0; k < 64; k++) {
            float p0 = Ss[(ty4 + 0) * 64 + k];
            float p1 = Ss[(ty4 + 1) * 64 + k];
            float p2 = Ss[(ty4 + 2) * 64 + k];
            float p3 = Ss[(ty4 + 3) * 64 + k];
            float4 va = *(const float4*)&KV[k * 128 + tx * 8];
            float4 vb = *(const float4*)&KV[k * 128 + tx * 8 + 4];
            Oa[0][0] += p0 * va.x; Oa[0][1] += p0 * va.y; Oa[0][2] += p0 * va.z; Oa[0][3] += p0 * va.w;
            Oa[0][4] += p0 * vb.x; Oa[0][5] += p0 * vb.y; Oa[0][6] += p0 * vb.z; Oa[0][7] += p0 * vb.w;
            Oa[1][0] += p1 * va.x; Oa[1][1] += p1 * va.y; Oa[1][2] += p1 * va.z; Oa[1][3] += p1 * va.w;
            Oa[1][4] += p1 * vb.x; Oa[1][5] += p1 * vb.y; Oa[1][6] += p1 * vb.z; Oa[1][7] += p1 * vb.w;
            Oa[2][0] += p2 * va.x; Oa[2][1] += p2 * va.y; Oa[2][2] += p2 * va.z; Oa[2][3] += p2 * va.w;
            Oa[2][4] += p2 * vb.x; Oa[2][5] += p2 * vb.y; Oa[2][6] += p2 * vb.z; Oa[2][7] += p2 * vb.w;
            Oa[3][0] += p3 * va.x; Oa[3][1] += p3 * va.y; Oa[3][2] += p3 * va.z; Oa[3][3] += p3 * va.w;
            Oa[3][4] += p3 * vb.x; Oa[3][5] += p3 * vb.y; Oa[3][6] += p3 * vb.z; Oa[3][7] += p3 * vb.w;
        }
    }

    // ---- epilogue: normalize and write to original (unshifted) positions ----
#pragma unroll
    for (int i = 0; i < 4; i++) {
        float inv = 1.0f / l[i];
        int srow = (base + qt * 64 + ty4 + i) & (S_LEN - 1);
        float4 o0 = make_float4(Oa[i][0] * inv, Oa[i][1] * inv, Oa[i][2] * inv, Oa[i][3] * inv);
        float4 o1 = make_float4(Oa[i][4] * inv, Oa[i][5] * inv, Oa[i][6] * inv, Oa[i][7] * inv);
        *(float4*)(Og + (size_t)srow * HDIM + tx * 8) = o0;
        *(float4*)(Og + (size_t)srow * HDIM + tx * 8 + 4) = o1;
    }
}

// ---------------- launch ----------------
extern "C" void kernel_launch(void* const* d_in, const int* in_sizes, int n_in,
                              void* d_out, int out_size) {
    const float* hs = (const float*)d_in[0];
    // d_in[1] = attention_mask: exactly causal per group; applied analytically.
    const int* pos = (const int*)d_in[2];
    const float* Wq = (const float*)d_in[3];
    const float* Wk = (const float*)d_in[4];
    const float* Wv = (const float*)d_in[5];
    const float* Wo = (const float*)d_in[6];
    float* out = (float*)d_out;

    float *Qp, *Kp, *Vp, *Op;
    cudaGetSymbolAddress((void**)&Qp, g_Q);
    cudaGetSymbolAddress((void**)&Kp, g_K);
    cudaGetSymbolAddress((void**)&Vp, g_V);
    cudaGetSymbolAddress((void**)&Op, g_O);

    cudaFuncSetAttribute(flash_kernel, cudaFuncAttributeMaxDynamicSharedMemorySize, FA_SMEM);

    rope_table_kernel<<<(S_LEN * 64 + 255) / 256, 256>>>();

    sgemm<<<dim3(HDIM / 128, MROWS / 128), 256>>>(hs, Wq, Qp, MROWS, HDIM, HDIM);
    sgemm<<<dim3(KVDIM / 128, MROWS / 128), 256>>>(hs, Wk, Kp, MROWS, KVDIM, HDIM);
    sgemm<<<dim3(KVDIM / 128, MROWS / 128), 256>>>(hs, Wv, Vp, MROWS, KVDIM, HDIM);

    rope_kernel<<<MROWS, 256>>>(pos);

    flash_kernel<<<dim3(GRP / 64, NHEAD, BATCH * NG), 256, FA_SMEM>>>();

    sgemm<<<dim3(HDIM / 128, MROWS / 128), 256>>>(Op, Wo, out, MROWS, HDIM, HDIM);
}

// round 7
// speedup vs baseline: 1.1786x; 1.1786x over previous
#include <cuda_runtime.h>
#include <math.h>

// ---------------- problem constants ----------------
#define S_LEN 4096
#define BATCH 2
#define NHEAD 16
#define NKVH  4
#define HD    128
#define HDIM  2048      // NHEAD*HD
#define KVDIM 512       // NKVH*HD
#define GRP   1024      // g = S * 0.25
#define NG    4         // S / g
#define MROWS (BATCH*S_LEN)   // 8192

// ---------------- scratch (device globals: no cudaMalloc allowed) ----------------
__device__ float g_Q[(size_t)MROWS * HDIM];    // 64 MB
__device__ float g_K[(size_t)MROWS * KVDIM];   // 16 MB
__device__ float g_V[(size_t)MROWS * KVDIM];   // 16 MB
__device__ float g_O[(size_t)MROWS * HDIM];    // 64 MB
__device__ float g_cos[S_LEN * 64];
__device__ float g_sin[S_LEN * 64];

// ---------------- RoPE table ----------------
__global__ void rope_table_kernel() {
    int idx = blockIdx.x * 256 + threadIdx.x;
    if (idx >= S_LEN * 64) return;
    int pos = idx >> 6;
    int i   = idx & 63;
    double inv = pow(10000.0, -((double)(2 * i) / 128.0));
    float ang = (float)pos * (float)inv;
    g_cos[idx] = (float)cos((double)ang);
    g_sin[idx] = (float)sin((double)ang);
}

// ---------------- RoPE apply (in place on g_Q, g_K) ----------------
__global__ void rope_kernel(const int* __restrict__ pos_ids) {
    int row = blockIdx.x;            // b*S + s
    int pos = pos_ids[row];
    int tid = threadIdx.x;
    for (int p = tid; p < NHEAD * 64; p += 256) {
        int hh = p >> 6, i = p & 63;
        float c  = g_cos[pos * 64 + i];
        float sn = g_sin[pos * 64 + i];
        size_t ba = (size_t)row * HDIM + hh * HD + i;
        float x0 = g_Q[ba], x1 = g_Q[ba + 64];
        g_Q[ba]      = x0 * c - x1 * sn;
        g_Q[ba + 64] = x1 * c + x0 * sn;
    }
    for (int p = tid; p < NKVH * 64; p += 256) {
        int hh = p >> 6, i = p & 63;
        float c  = g_cos[pos * 64 + i];
        float sn = g_sin[pos * 64 + i];
        size_t ba = (size_t)row * KVDIM + hh * HD + i;
        float x0 = g_K[ba], x1 = g_K[ba + 64];
        g_K[ba]      = x0 * c - x1 * sn;
        g_K[ba + 64] = x1 * c + x0 * sn;
    }
}

// ---------------- fp32 SGEMM, double-buffered: C[M,N] = A[M,K] @ B[K,N] ----------------
// BM=BN=128, BK=8, 256 threads, 8x8 register tile, 1 __syncthreads per K-step.
__global__ __launch_bounds__(256) void sgemm(const float* __restrict__ A,
                                             const float* __restrict__ B,
                                             float* __restrict__ C,
                                             int M, int N, int K) {
    __shared__ float As[2][8][128];
    __shared__ float Bs[2][8][128];
    int tid = threadIdx.x;
    int bm = blockIdx.y * 128, bn = blockIdx.x * 128;
    int arow = tid >> 1, acol = (tid & 1) * 4;
    int brow = tid >> 5, bcol = (tid & 31) * 4;
    int tx = tid & 15, ty = tid >> 4;

    const float* Ap = A + (size_t)(bm + arow) * K + acol;
    const float* Bp = B + (size_t)brow * N + bn + bcol;

    float acc[8][8];
#pragma unroll
    for (int i = 0; i < 8; i++)
#pragma unroll
        for (int j = 0; j < 8; j++) acc[i][j] = 0.f;

    // prologue: stage tile 0 into buffer 0
    {
        float4 av = *(const float4*)(Ap);
        float4 bv = *(const float4*)(Bp);
        As[0][acol + 0][arow] = av.x;
        As[0][acol + 1][arow] = av.y;
        As[0][acol + 2][arow] = av.z;
        As[0][acol + 3][arow] = av.w;
        *(float4*)&Bs[0][brow][bcol] = bv;
    }
    int buf = 0;

    for (int k0 = 0; k0 < K; k0 += 8) {
        bool has_next = (k0 + 8) < K;
        float4 a2, b2;
        if (has_next) {
            a2 = *(const float4*)(Ap + k0 + 8);
            b2 = *(const float4*)(Bp + (size_t)(k0 + 8) * N);
        }
        __syncthreads();   // buf writes visible; prior reads of buf^1 complete
#pragma unroll
        for (int kk = 0; kk < 8; kk++) {
            float ra[8], rb[8];
            *(float4*)&ra[0] = *(const float4*)&As[buf][kk][ty * 8];
            *(float4*)&ra[4] = *(const float4*)&As[buf][kk][ty * 8 + 4];
            *(float4*)&rb[0] = *(const float4*)&Bs[buf][kk][tx * 8];
            *(float4*)&rb[4] = *(const float4*)&Bs[buf][kk][tx * 8 + 4];
#pragma unroll
            for (int i = 0; i < 8; i++)
#pragma unroll
                for (int j = 0; j < 8; j++) acc[i][j] += ra[i] * rb[j];
        }
        if (has_next) {
            int nb = buf ^ 1;
            As[nb][acol + 0][arow] = a2.x;
            As[nb][acol + 1][arow] = a2.y;
            As[nb][acol + 2][arow] = a2.z;
            As[nb][acol + 3][arow] = a2.w;
            *(float4*)&Bs[nb][brow][bcol] = b2;
        }
        buf ^= 1;
    }
#pragma unroll
    for (int i = 0; i < 8; i++) {
        float* cp = C + (size_t)(bm + ty * 8 + i) * N + bn + tx * 8;
        float4 v0 = make_float4(acc[i][0], acc[i][1], acc[i][2], acc[i][3]);
        float4 v1 = make_float4(acc[i][4], acc[i][5], acc[i][6], acc[i][7]);
        *(float4*)cp = v0;
        *(float4*)(cp + 4) = v1;
    }
}

// ---------------- flash attention over S2 groups ----------------
// grid (16 qtiles, 16 heads, 8 group-blocks), 256 threads.
// BM=BN=64. Smem: Qs[64][128], KV union (K^T[128][64] / V[64][128]), Ss[64][64]
// 80 KB dynamic smem -> 2 CTAs/SM (160 KB of 228 KB).
#define FA_SMEM ((64 * 128 + 64 * 128 + 64 * 64) * 4)

__global__ __launch_bounds__(256, 2) void flash_kernel() {
    extern __shared__ float smf[];
    float* Qs = smf;                 // [64][128]
    float* KV = smf + 64 * 128;      // K^T: [d][c] stride 64  OR  V: [k][c] stride 128
    float* Ss = smf + 2 * 64 * 128;  // [64][64]

    int tid = threadIdx.x;
    int qt = blockIdx.x;      // query tile within group
    int h  = blockIdx.y;      // head
    int bg = blockIdx.z;      // b*NG + gi
    int b = bg >> 2, gi = bg & 3;
    int base = gi * GRP + ((h >= NHEAD / 2) ? (GRP / 2) : 0);  // S2 shift
    int kvh = h >> 2;                                          // GQA map

    const float* Qg = g_Q + (size_t)b * S_LEN * HDIM + h * HD;
    const float* Kg = g_K + (size_t)b * S_LEN * KVDIM + kvh * HD;
    const float* Vg = g_V + (size_t)b * S_LEN * KVDIM + kvh * HD;
    float* Og = g_O + (size_t)b * S_LEN * HDIM + h * HD;

    int tx = tid & 15, ty = tid >> 4;
    int ty4 = ty * 4;

    // load Q tile (coalesced float4)
#pragma unroll
    for (int it = 0; it < 8; it++) {
        int idx = it * 1024 + tid * 4;
        int r = idx >> 7, c = idx & 127;
        int srow = (base + qt * 64 + r) & (S_LEN - 1);
        *(float4*)&Qs[r * 128 + c] = *(const float4*)(Qg + (size_t)srow * HDIM + c);
    }

    float m[4], l[4], Oa[4][8];
#pragma unroll
    for (int i = 0; i < 4; i++) {
        m[i] = -1e30f;
        l[i] = 0.f;
#pragma unroll
        for (int j = 0; j < 8; j++) Oa[i][j] = 0.f;
    }

    for (int kt = 0; kt <= qt; kt++) {
        __syncthreads();  // prior PV / Q-load complete
        // ---- load K tile transposed: KV[d*64 + c] = K[c][d] ----
        {
            int r = tid & 63, dblk = tid >> 6;
            int srow = (base + kt * 64 + r) & (S_LEN - 1);
            const float* kp = Kg + (size_t)srow * KVDIM;
#pragma unroll
            for (int it = 0; it < 8; it++) {
                int d0 = dblk * 32 + it * 4;
                float4 v = *(const float4*)(kp + d0);
                KV[(d0 + 0) * 64 + r] = v.x;
                KV[(d0 + 1) * 64 + r] = v.y;
                KV[(d0 + 2) * 64 + r] = v.z;
                KV[(d0 + 3) * 64 + r] = v.w;
            }
        }
        __syncthreads();

        // ---- S = Q K^T (4x4 register tile per thread) ----
        float sa[4][4];
#pragma unroll
        for (int i = 0; i < 4; i++)
#pragma unroll
            for (int j = 0; j < 4; j++) sa[i][j] = 0.f;

        for (int d4 = 0; d4 < 128; d4 += 4) {
            float qa[4][4];
#pragma unroll
            for (int i = 0; i < 4; i++)
                *(float4*)qa[i] = *(const float4*)&Qs[(ty4 + i) * 128 + d4];
#pragma unroll
            for (int dd = 0; dd < 4; dd++) {
                float4 kvv = *(const float4*)&KV[(d4 + dd) * 64 + tx * 4];
#pragma unroll
                for (int i = 0; i < 4; i++) {
                    sa[i][0] += qa[i][dd] * kvv.x;
                    sa[i][1] += qa[i][dd] * kvv.y;
                    sa[i][2] += qa[i][dd] * kvv.z;
                    sa[i][3] += qa[i][dd] * kvv.w;
                }
            }
        }

        // ---- scale + causal mask + online softmax ----
        const float scale = 0.08838834764831845f;  // 1/sqrt(128)
        int qb = qt * 64 + ty4, kb = kt * 64 + tx * 4;
#pragma unroll
        for (int i = 0; i < 4; i++) {
#pragma unroll
            for (int j = 0; j < 4; j++) {
                float v = sa[i][j] * scale;
                if (kb + j > qb + i) v = -1e30f;
                sa[i][j] = v;
            }
            float mx = fmaxf(fmaxf(sa[i][0], sa[i][1]), fmaxf(sa[i][2], sa[i][3]));
#pragma unroll
            for (int o = 1; o < 16; o <<= 1)
                mx = fmaxf(mx, __shfl_xor_sync(0xffffffffu, mx, o));
            float mn = fmaxf(m[i], mx);
            float sc = expf(m[i] - mn);
            float rs = 0.f;
#pragma unroll
            for (int j = 0; j < 4; j++) {
                float p = expf(sa[i][j] - mn);
                sa[i][j] = p;
                rs += p;
            }
#pragma unroll
            for (int o = 1; o < 16; o <<= 1)
                rs += __shfl_xor_sync(0xffffffffu, rs, o);
            l[i] = l[i] * sc + rs;
            m[i] = mn;
#pragma unroll
            for (int j = 0; j < 8; j++) Oa[i][j] *= sc;
            *(float4*)&Ss[(ty4 + i) * 64 + tx * 4] = *(float4*)sa[i];
        }
        __syncthreads();  // Ss visible; done reading K from KV

        // ---- load V tile (normal layout, coalesced) ----
#pragma unroll
        for (int it = 0; it < 8; it++) {
            int idx = it * 1024 + tid * 4;
            int r = idx >> 7, c = idx & 127;
            int srow = (base + kt * 64 + r) & (S_LEN - 1);
            *(float4*)&KV[r * 128 + c] = *(const float4*)(Vg + (size_t)srow * KVDIM + c);
        }
        __syncthreads();

        // ---- O += P @ V (rows ty4..+3, cols tx*8..+7) ----
#pragma unroll 8
        for (int k = 0; k < 64; k++) {
            float p0 = Ss[(ty4 + 0) * 64 + k];
            float p1 = Ss[(ty4 + 1) * 64 + k];
            float p2 = Ss[(ty4 + 2) * 64 + k];
            float p3 = Ss[(ty4 + 3) * 64 + k];
            float4 va = *(const float4*)&KV[k * 128 + tx * 8];
            float4 vb = *(const float4*)&KV[k * 128 + tx * 8 + 4];
            Oa[0][0] += p0 * va.x; Oa[0][1] += p0 * va.y; Oa[0][2] += p0 * va.z; Oa[0][3] += p0 * va.w;
            Oa[0][4] += p0 * vb.x; Oa[0][5] += p0 * vb.y; Oa[0][6] += p0 * vb.z; Oa[0][7] += p0 * vb.w;
            Oa[1][0] += p1 * va.x; Oa[1][1] += p1 * va.y; Oa[1][2] += p1 * va.z; Oa[1][3] += p1 * va.w;
            Oa[1][4] += p1 * vb.x; Oa[1][5] += p1 * vb.y; Oa[1][6] += p1 * vb.z; Oa[1][7] += p1 * vb.w;
            Oa[2][0] += p2 * va.x; Oa[2][1] += p2 * va.y; Oa[2][2] += p2 * va.z; Oa[2][3] += p2 * va.w;
            Oa[2][4] += p2 * vb.x; Oa[2][5] += p2 * vb.y; Oa[2][6] += p2 * vb.z; Oa[2][7] += p2 * vb.w;
            Oa[3][0] += p3 * va.x; Oa[3][1] += p3 * va.y; Oa[3][2] += p3 * va.z; Oa[3][3] += p3 * va.w;
            Oa[3][4] += p3 * vb.x; Oa[3][5] += p3 * vb.y; Oa[3][6] += p3 * vb.z; Oa[3][7] += p3 * vb.w;
        }
    }

    // ---- epilogue: normalize and write to original (unshifted) positions ----
#pragma unroll
    for (int i = 0; i < 4; i++) {
        float inv = 1.0f / l[i];
        int srow = (base + qt * 64 + ty4 + i) & (S_LEN - 1);
        float4 o0 = make_float4(Oa[i][0] * inv, Oa[i][1] * inv, Oa[i][2] * inv, Oa[i][3] * inv);
        float4 o1 = make_float4(Oa[i][4] * inv, Oa[i][5] * inv, Oa[i][6] * inv, Oa[i][7] * inv);
        *(float4*)(Og + (size_t)srow * HDIM + tx * 8) = o0;
        *(float4*)(Og + (size_t)srow * HDIM + tx * 8 + 4) = o1;
    }
}

// ---------------- launch ----------------
extern "C" void kernel_launch(void* const* d_in, const int* in_sizes, int n_in,
                              void* d_out, int out_size) {
    const float* hs = (const float*)d_in[0];
    // d_in[1] = attention_mask: exactly causal per group; applied analytically.
    const int* pos = (const int*)d_in[2];
    const float* Wq = (const float*)d_in[3];
    const float* Wk = (const float*)d_in[4];
    const float* Wv = (const float*)d_in[5];
    const float* Wo = (const float*)d_in[6];
    float* out = (float*)d_out;

    float *Qp, *Kp, *Vp, *Op;
    cudaGetSymbolAddress((void**)&Qp, g_Q);
    cudaGetSymbolAddress((void**)&Kp, g_K);
    cudaGetSymbolAddress((void**)&Vp, g_V);
    cudaGetSymbolAddress((void**)&Op, g_O);

    cudaFuncSetAttribute(flash_kernel, cudaFuncAttributeMaxDynamicSharedMemorySize, FA_SMEM);

    rope_table_kernel<<<(S_LEN * 64 + 255) / 256, 256>>>();

    sgemm<<<dim3(HDIM / 128, MROWS / 128), 256>>>(hs, Wq, Qp, MROWS, HDIM, HDIM);
    sgemm<<<dim3(KVDIM / 128, MROWS / 128), 256>>>(hs, Wk, Kp, MROWS, KVDIM, HDIM);
    sgemm<<<dim3(KVDIM / 128, MROWS / 128), 256>>>(hs, Wv, Vp, MROWS, KVDIM, HDIM);

    rope_kernel<<<MROWS, 256>>>(pos);

    flash_kernel<<<dim3(GRP / 64, NHEAD, BATCH * NG), 256, FA_SMEM>>>();

    sgemm<<<dim3(HDIM / 128, MROWS / 128), 256>>>(Op, Wo, out, MROWS, HDIM, HDIM);
}

// round 16
// speedup vs baseline: 1.2586x; 1.0679x over previous
#include <cuda_runtime.h>
#include <math.h>

// ---------------- problem constants ----------------
#define S_LEN 4096
#define BATCH 2
#define NHEAD 16
#define NKVH  4
#define HD    128
#define HDIM  2048      // NHEAD*HD
#define KVDIM 512       // NKVH*HD
#define GRP   1024      // g = S * 0.25
#define NG    4         // S / g
#define MROWS (BATCH*S_LEN)   // 8192

// flash tiling
#define BM 128
#define BN 128
#define NQT (GRP / BM)        // 8
#define QS_STR 132            // padded row stride (floats), 528B = 33*16 (f4-aligned)
#define SS_STR 132

// ---------------- scratch (device globals: no cudaMalloc allowed) ----------------
__device__ float g_Q[(size_t)MROWS * HDIM];    // 64 MB
__device__ float g_K[(size_t)MROWS * KVDIM];   // 16 MB
__device__ float g_V[(size_t)MROWS * KVDIM];   // 16 MB
__device__ float g_O[(size_t)MROWS * HDIM];    // 64 MB
__device__ float g_cos[S_LEN * 64];
__device__ float g_sin[S_LEN * 64];

// ---------------- RoPE table ----------------
__global__ void rope_table_kernel() {
    int idx = blockIdx.x * 256 + threadIdx.x;
    if (idx >= S_LEN * 64) return;
    int pos = idx >> 6;
    int i   = idx & 63;
    double inv = pow(10000.0, -((double)(2 * i) / 128.0));
    float ang = (float)pos * (float)inv;
    g_cos[idx] = (float)cos((double)ang);
    g_sin[idx] = (float)sin((double)ang);
}

// ---------------- RoPE apply (in place on g_Q, g_K) ----------------
__global__ void rope_kernel(const int* __restrict__ pos_ids) {
    int row = blockIdx.x;            // b*S + s
    int pos = pos_ids[row];
    int tid = threadIdx.x;
    for (int p = tid; p < NHEAD * 64; p += 256) {
        int hh = p >> 6, i = p & 63;
        float c  = g_cos[pos * 64 + i];
        float sn = g_sin[pos * 64 + i];
        size_t ba = (size_t)row * HDIM + hh * HD + i;
        float x0 = g_Q[ba], x1 = g_Q[ba + 64];
        g_Q[ba]      = x0 * c - x1 * sn;
        g_Q[ba + 64] = x1 * c + x0 * sn;
    }
    for (int p = tid; p < NKVH * 64; p += 256) {
        int hh = p >> 6, i = p & 63;
        float c  = g_cos[pos * 64 + i];
        float sn = g_sin[pos * 64 + i];
        size_t ba = (size_t)row * KVDIM + hh * HD + i;
        float x0 = g_K[ba], x1 = g_K[ba + 64];
        g_K[ba]      = x0 * c - x1 * sn;
        g_K[ba + 64] = x1 * c + x0 * sn;
    }
}

// ---------------- fp32 SGEMM, double-buffered ----------------
__global__ __launch_bounds__(256) void sgemm(const float* __restrict__ A,
                                             const float* __restrict__ B,
                                             float* __restrict__ C,
                                             int M, int N, int K) {
    __shared__ float As[2][8][128];
    __shared__ float Bs[2][8][128];
    int tid = threadIdx.x;
    int bm = blockIdx.y * 128, bn = blockIdx.x * 128;
    int arow = tid >> 1, acol = (tid & 1) * 4;
    int brow = tid >> 5, bcol = (tid & 31) * 4;
    int tx = tid & 15, ty = tid >> 4;

    const float* Ap = A + (size_t)(bm + arow) * K + acol;
    const float* Bp = B + (size_t)brow * N + bn + bcol;

    float acc[8][8];
#pragma unroll
    for (int i = 0; i < 8; i++)
#pragma unroll
        for (int j = 0; j < 8; j++) acc[i][j] = 0.f;

    {
        float4 av = *(const float4*)(Ap);
        float4 bv = *(const float4*)(Bp);
        As[0][acol + 0][arow] = av.x;
        As[0][acol + 1][arow] = av.y;
        As[0][acol + 2][arow] = av.z;
        As[0][acol + 3][arow] = av.w;
        *(float4*)&Bs[0][brow][bcol] = bv;
    }
    int buf = 0;

    for (int k0 = 0; k0 < K; k0 += 8) {
        bool has_next = (k0 + 8) < K;
        float4 a2, b2;
        if (has_next) {
            a2 = *(const float4*)(Ap + k0 + 8);
            b2 = *(const float4*)(Bp + (size_t)(k0 + 8) * N);
        }
        __syncthreads();
#pragma unroll
        for (int kk = 0; kk < 8; kk++) {
            float ra[8], rb[8];
            *(float4*)&ra[0] = *(const float4*)&As[buf][kk][ty * 8];
            *(float4*)&ra[4] = *(const float4*)&As[buf][kk][ty * 8 + 4];
            *(float4*)&rb[0] = *(const float4*)&Bs[buf][kk][tx * 8];
            *(float4*)&rb[4] = *(const float4*)&Bs[buf][kk][tx * 8 + 4];
#pragma unroll
            for (int i = 0; i < 8; i++)
#pragma unroll
                for (int j = 0; j < 8; j++) acc[i][j] += ra[i] * rb[j];
        }
        if (has_next) {
            int nb = buf ^ 1;
            As[nb][acol + 0][arow] = a2.x;
            As[nb][acol + 1][arow] = a2.y;
            As[nb][acol + 2][arow] = a2.z;
            As[nb][acol + 3][arow] = a2.w;
            *(float4*)&Bs[nb][brow][bcol] = b2;
        }
        buf ^= 1;
    }
#pragma unroll
    for (int i = 0; i < 8; i++) {
        float* cp = C + (size_t)(bm + ty * 8 + i) * N + bn + tx * 8;
        float4 v0 = make_float4(acc[i][0], acc[i][1], acc[i][2], acc[i][3]);
        float4 v1 = make_float4(acc[i][4], acc[i][5], acc[i][6], acc[i][7]);
        *(float4*)cp = v0;
        *(float4*)(cp + 4) = v1;
    }
}

// ---------------- flash attention v2: BM=BN=128, 8x8 register tiles ----------------
// grid (8 bg, 16 heads, 8 qt[desc]), 256 threads, 1 CTA/SM (~196KB smem).
// Smem: Qs[128][132], KV union (K^T[128 d][128 c] / V[128 k][128 c]), Ss[128][132]
#define FA_SMEM ((BM * QS_STR + BN * 128 + BM * SS_STR) * 4)

__global__ __launch_bounds__(256, 1) void flash_kernel() {
    extern __shared__ float smf[];
    float* Qs = smf;                          // [128][QS_STR]
    float* KV = smf + BM * QS_STR;            // K^T [d][c] str 128 / V [k][c] str 128
    float* Ss = smf + BM * QS_STR + BN * 128; // [128][SS_STR]

    int tid = threadIdx.x;
    int tx = tid & 15, ty = tid >> 4;
    int qt = (NQT - 1) - blockIdx.z;   // longest blocks first (LPT)
    int h  = blockIdx.y;
    int bg = blockIdx.x;
    int b = bg >> 2, gi = bg & 3;
    int base = gi * GRP + ((h >= NHEAD / 2) ? (GRP / 2) : 0);  // S2 shift
    int kvh = h >> 2;                                          // GQA map

    const float* Qg = g_Q + (size_t)b * S_LEN * HDIM + h * HD;
    const float* Kg = g_K + (size_t)b * S_LEN * KVDIM + kvh * HD;
    const float* Vg = g_V + (size_t)b * S_LEN * KVDIM + kvh * HD;
    float* Og = g_O + (size_t)b * S_LEN * HDIM + h * HD;

    // ---- load Q tile [128][128] ----
#pragma unroll
    for (int it = 0; it < 16; it++) {
        int idx = it * 1024 + tid * 4;
        int r = idx >> 7, c = idx & 127;
        int srow = (base + qt * BM + r) & (S_LEN - 1);
        *(float4*)&Qs[r * QS_STR + c] = *(const float4*)(Qg + (size_t)srow * HDIM + c);
    }

    float m[8], l[8], Oa[8][8];
#pragma unroll
    for (int i = 0; i < 8; i++) {
        m[i] = -1e30f;
        l[i] = 0.f;
#pragma unroll
        for (int j = 0; j < 8; j++) Oa[i][j] = 0.f;
    }

    for (int kt = 0; kt <= qt; kt++) {
        __syncthreads();  // prior PV / Q-load complete
        // ---- load K tile transposed: KV[d*128 + c] = K[c][d] ----
        {
            int r = tid & 127, dh = tid >> 7;   // dh in {0,1}: d-half
            int srow = (base + kt * BN + r) & (S_LEN - 1);
            const float* kp = Kg + (size_t)srow * KVDIM + dh * 64;
#pragma unroll
            for (int it = 0; it < 16; it++) {
                int d0 = dh * 64 + it * 4;
                float4 v = *(const float4*)(kp + it * 4);
                KV[(d0 + 0) * 128 + r] = v.x;
                KV[(d0 + 1) * 128 + r] = v.y;
                KV[(d0 + 2) * 128 + r] = v.z;
                KV[(d0 + 3) * 128 + r] = v.w;
            }
        }
        __syncthreads();

        // ---- S = Q K^T (8x8 register tile) ----
        float sa[8][8];
#pragma unroll
        for (int i = 0; i < 8; i++)
#pragma unroll
            for (int j = 0; j < 8; j++) sa[i][j] = 0.f;

        for (int d4 = 0; d4 < HD; d4 += 4) {
            float qa[8][4];
#pragma unroll
            for (int i = 0; i < 8; i++)
                *(float4*)qa[i] = *(const float4*)&Qs[(ty * 8 + i) * QS_STR + d4];
#pragma unroll
            for (int dd = 0; dd < 4; dd++) {
                float4 k0 = *(const float4*)&KV[(d4 + dd) * 128 + tx * 8];
                float4 k1 = *(const float4*)&KV[(d4 + dd) * 128 + tx * 8 + 4];
#pragma unroll
                for (int i = 0; i < 8; i++) {
                    float q = qa[i][dd];
                    sa[i][0] += q * k0.x; sa[i][1] += q * k0.y;
                    sa[i][2] += q * k0.z; sa[i][3] += q * k0.w;
                    sa[i][4] += q * k1.x; sa[i][5] += q * k1.y;
                    sa[i][6] += q * k1.z; sa[i][7] += q * k1.w;
                }
            }
        }

        // ---- scale + (diag-only) causal mask + online softmax ----
        const float scale = 0.08838834764831845f;  // 1/sqrt(128)
        bool diag = (kt == qt);
#pragma unroll
        for (int i = 0; i < 8; i++) {
            int row = ty * 8 + i;
            if (diag) {
#pragma unroll
                for (int j = 0; j < 8; j++) {
                    float v = sa[i][j] * scale;
                    if (tx * 8 + j > row) v = -1e30f;
                    sa[i][j] = v;
                }
            } else {
#pragma unroll
                for (int j = 0; j < 8; j++) sa[i][j] *= scale;
            }
            float mx = sa[i][0];
#pragma unroll
            for (int j = 1; j < 8; j++) mx = fmaxf(mx, sa[i][j]);
#pragma unroll
            for (int o = 1; o < 16; o <<= 1)
                mx = fmaxf(mx, __shfl_xor_sync(0xffffffffu, mx, o));
            float mn = fmaxf(m[i], mx);
            float sc = __expf(m[i] - mn);
            float rs = 0.f;
#pragma unroll
            for (int j = 0; j < 8; j++) {
                float p = __expf(sa[i][j] - mn);
                sa[i][j] = p;
                rs += p;
            }
#pragma unroll
            for (int o = 1; o < 16; o <<= 1)
                rs += __shfl_xor_sync(0xffffffffu, rs, o);
            l[i] = l[i] * sc + rs;
            m[i] = mn;
#pragma unroll
            for (int j = 0; j < 8; j++) Oa[i][j] *= sc;
            *(float4*)&Ss[row * SS_STR + tx * 8]     = *(float4*)&sa[i][0];
            *(float4*)&Ss[row * SS_STR + tx * 8 + 4] = *(float4*)&sa[i][4];
        }
        __syncthreads();  // Ss visible; done reading K from KV

        // ---- load V tile [128][128] ----
#pragma unroll
        for (int it = 0; it < 16; it++) {
            int idx = it * 1024 + tid * 4;
            int r = idx >> 7, c = idx & 127;
            int srow = (base + kt * BN + r) & (S_LEN - 1);
            *(float4*)&KV[r * 128 + c] = *(const float4*)(Vg + (size_t)srow * KVDIM + c);
        }
        __syncthreads();

        // ---- O += P @ V ----
        for (int k4 = 0; k4 < BN; k4 += 4) {
            float ps[8][4];
#pragma unroll
            for (int i = 0; i < 8; i++)
                *(float4*)ps[i] = *(const float4*)&Ss[(ty * 8 + i) * SS_STR + k4];
#pragma unroll
            for (int kk = 0; kk < 4; kk++) {
                float4 va = *(const float4*)&KV[(k4 + kk) * 128 + tx * 8];
                float4 vb = *(const float4*)&KV[(k4 + kk) * 128 + tx * 8 + 4];
#pragma unroll
                for (int i = 0; i < 8; i++) {
                    float p = ps[i][kk];
                    Oa[i][0] += p * va.x; Oa[i][1] += p * va.y;
                    Oa[i][2] += p * va.z; Oa[i][3] += p * va.w;
                    Oa[i][4] += p * vb.x; Oa[i][5] += p * vb.y;
                    Oa[i][6] += p * vb.z; Oa[i][7] += p * vb.w;
                }
            }
        }
    }

    // ---- epilogue: normalize, write to original (unshifted) positions ----
#pragma unroll
    for (int i = 0; i < 8; i++) {
        float inv = 1.0f / l[i];
        int srow = (base + qt * BM + ty * 8 + i) & (S_LEN - 1);
        float4 o0 = make_float4(Oa[i][0] * inv, Oa[i][1] * inv, Oa[i][2] * inv, Oa[i][3] * inv);
        float4 o1 = make_float4(Oa[i][4] * inv, Oa[i][5] * inv, Oa[i][6] * inv, Oa[i][7] * inv);
        *(float4*)(Og + (size_t)srow * HDIM + tx * 8) = o0;
        *(float4*)(Og + (size_t)srow * HDIM + tx * 8 + 4) = o1;
    }
}

// ---------------- launch ----------------
extern "C" void kernel_launch(void* const* d_in, const int* in_sizes, int n_in,
                              void* d_out, int out_size) {
    const float* hs = (const float*)d_in[0];
    // d_in[1] = attention_mask: exactly causal per group; applied analytically.
    const int* pos = (const int*)d_in[2];
    const float* Wq = (const float*)d_in[3];
    const float* Wk = (const float*)d_in[4];
    const float* Wv = (const float*)d_in[5];
    const float* Wo = (const float*)d_in[6];
    float* out = (float*)d_out;

    float *Qp, *Kp, *Vp, *Op;
    cudaGetSymbolAddress((void**)&Qp, g_Q);
    cudaGetSymbolAddress((void**)&Kp, g_K);
    cudaGetSymbolAddress((void**)&Vp, g_V);
    cudaGetSymbolAddress((void**)&Op, g_O);

    cudaFuncSetAttribute(flash_kernel, cudaFuncAttributeMaxDynamicSharedMemorySize, FA_SMEM);

    rope_table_kernel<<<(S_LEN * 64 + 255) / 256, 256>>>();

    sgemm<<<dim3(HDIM / 128, MROWS / 128), 256>>>(hs, Wq, Qp, MROWS, HDIM, HDIM);
    sgemm<<<dim3(KVDIM / 128, MROWS / 128), 256>>>(hs, Wk, Kp, MROWS, KVDIM, HDIM);
    sgemm<<<dim3(KVDIM / 128, MROWS / 128), 256>>>(hs, Wv, Vp, MROWS, KVDIM, HDIM);

    rope_kernel<<<MROWS, 256>>>(pos);

    flash_kernel<<<dim3(BATCH * NG, NHEAD, NQT), 256, FA_SMEM>>>();

    sgemm<<<dim3(HDIM / 128, MROWS / 128), 256>>>(Op, Wo, out, MROWS, HDIM, HDIM);
}